// round 3
// baseline (speedup 1.0000x reference)
#include <cuda_runtime.h>
#include <cuda_bf16.h>

// out[i] = sum_k targets[i,k] * temporal_bases[batch_indices[1], k] * scaling[k]
// B=8192, K=1024, T=16384. Pure HBM-streaming GEMV: read targets once (32 MB).
// batch_indices is int32 (jax canonicalizes int64 -> int32 without x64 mode).

static constexpr int K = 1024;
static constexpr int THREADS = 256;   // 256 * 4 floats = 1024 = K

__global__ __launch_bounds__(THREADS, 8)
void recompose_gemv_kernel(const float* __restrict__ targets,
                           const float* __restrict__ bases,
                           const float* __restrict__ scaling,
                           const int* __restrict__ batch_indices,
                           int T,
                           float* __restrict__ out) {
    const int row = blockIdx.x;
    int t = batch_indices[1];                      // L2-broadcast across all CTAs
    t = min(max(t, 0), T - 1);                     // never fault

    const float4* __restrict__ a4 = reinterpret_cast<const float4*>(targets + (size_t)row * K);
    const float4* __restrict__ b4 = reinterpret_cast<const float4*>(bases + (size_t)t * K);
    const float4* __restrict__ s4 = reinterpret_cast<const float4*>(scaling);

    const int i = threadIdx.x;                     // 0..255
    float4 a = a4[i];
    float4 b = b4[i];
    float4 s = s4[i];

    float sum = a.x * (b.x * s.x)
              + a.y * (b.y * s.y)
              + a.z * (b.z * s.z)
              + a.w * (b.w * s.w);

    // warp reduce
    #pragma unroll
    for (int off = 16; off > 0; off >>= 1)
        sum += __shfl_down_sync(0xffffffffu, sum, off);

    __shared__ float warp_sums[THREADS / 32];
    if ((threadIdx.x & 31) == 0)
        warp_sums[threadIdx.x >> 5] = sum;
    __syncthreads();

    if (threadIdx.x < (THREADS / 32)) {
        float v = warp_sums[threadIdx.x];
        #pragma unroll
        for (int off = (THREADS / 64); off > 0; off >>= 1)
            v += __shfl_down_sync(0xffu, v, off);
        if (threadIdx.x == 0)
            out[row] = v;
    }
}

extern "C" void kernel_launch(void* const* d_in, const int* in_sizes, int n_in,
                              void* d_out, int out_size) {
    // Resolve inputs by unique element counts, robust to metadata ordering.
    const float* targets = nullptr;   // B*K  = 8388608
    const float* bases   = nullptr;   // T*K  = 16777216
    const float* scaling = nullptr;   // K    = 1024
    const int*   indices = nullptr;   // B    = 8192
    long targets_n = 0, bases_n = 0;

    for (int j = 0; j < n_in; j++) {
        long n = in_sizes[j];
        if (n == K) {
            scaling = (const float*)d_in[j];
        } else if (n == 8192) {
            indices = (const int*)d_in[j];
        } else if (n == 8192L * K) {
            targets = (const float*)d_in[j];
            targets_n = n;
        } else {
            bases = (const float*)d_in[j];
            bases_n = n;
        }
    }
    if (!targets || !bases || !scaling || !indices) return;

    const int B = (int)(targets_n / K);   // 8192
    const int T = (int)(bases_n / K);     // 16384
    float* out = (float*)d_out;           // (B, 1) fp32

    recompose_gemv_kernel<<<B, THREADS>>>(targets, bases, scaling, indices, T, out);
}